// round 4
// baseline (speedup 1.0000x reference)
#include <cuda_runtime.h>

typedef unsigned int u32;
typedef unsigned long long u64;

#define M_TOT   16384          // 16 * 32 * 32 tiles
#define NAB     36

// Scratch (__device__ globals; no allocation allowed)
__device__ float g_V[(size_t)NAB * M_TOT * 64];   // V[ab][m][ci]
__device__ float g_M[(size_t)NAB * 64 * M_TOT];   // M[ab][co][m]
__device__ float g_Wt[NAB * 64 * 64];             // Wt[ab][co][ci]

__device__ __forceinline__ float to_tf32(float x) {
    u32 u;
    asm("cvt.rna.tf32.f32 %0, %1;" : "=r"(u) : "f"(x));
    return __uint_as_float(u);
}

// mma.sync m16n8k8 tf32 (legacy tensor path, valid on plain sm_103)
__device__ __forceinline__ void mma8(float* d, u32 a0, u32 a1, u32 a2, u32 a3,
                                     u32 b0, u32 b1) {
    asm volatile(
        "mma.sync.aligned.m16n8k8.row.col.f32.tf32.tf32.f32 "
        "{%0,%1,%2,%3}, {%4,%5,%6,%7}, {%8,%9}, {%0,%1,%2,%3};"
        : "+f"(d[0]), "+f"(d[1]), "+f"(d[2]), "+f"(d[3])
        : "r"(a0), "r"(a1), "r"(a2), "r"(a3), "r"(b0), "r"(b1));
}

// ---------------------------------------------------------------------------
// K1: weight prep  weight[co][ci][ab] -> Wt[ab][co][ci]
// ---------------------------------------------------------------------------
__global__ __launch_bounds__(256) void wt_kernel(const float* __restrict__ w) {
    int idx = blockIdx.x * 256 + threadIdx.x;      // ab*4096 + co*64 + ci
    if (idx >= NAB * 64 * 64) return;
    int ci = idx & 63;
    int co = (idx >> 6) & 63;
    int ab = idx >> 12;
    g_Wt[idx] = w[(co * 64 + ci) * 36 + ab];
}

// ---------------------------------------------------------------------------
// K2: input transform -> V[ab][m][ci]  (smem-staged x for coalescing)
// CTA = (n, p, 8 q-blocks of 4 tiles) x 64 ci.  256 threads.
// ---------------------------------------------------------------------------
__global__ __launch_bounds__(256) void in_transform(const float* __restrict__ x) {
    __shared__ float sx[64 * 109];   // [ci][h*18+w], pitch 109 (conflict-free)

    int b  = blockIdx.x;
    int qb = b & 7;
    int p  = (b >> 3) & 31;
    int n  = b >> 8;
    int tid = threadIdx.x;

    int h0 = p * 4 - 1;
    int w0 = qb * 16 - 1;

    // Stage x region: 6 h x 18 w x 64 ci = 6912 floats
#pragma unroll
    for (int k = 0; k < 27; k++) {
        int f = k * 256 + tid;
        int wl = f % 18;
        int u  = f / 18;
        int hl = u % 6;
        int ci = u / 6;
        int gh = h0 + hl, gw = w0 + wl;
        float val = 0.0f;
        if ((unsigned)gh < 128u && (unsigned)gw < 128u)
            val = x[((size_t)(n * 64 + ci) * 128 + gh) * 128 + gw];
        sx[ci * 109 + hl * 18 + wl] = val;
    }
    __syncthreads();

    int ci = tid & 63;
    int qt = tid >> 6;
    const float* dp = &sx[ci * 109 + qt * 4];

    float d[6][6];
#pragma unroll
    for (int i = 0; i < 6; i++)
#pragma unroll
        for (int j = 0; j < 6; j++)
            d[i][j] = dp[i * 18 + j];

    float t[6][6];
#pragma unroll
    for (int j = 0; j < 6; j++) {
        t[0][j] =  4.0f * d[0][j] - 5.0f * d[2][j] + d[4][j];
        t[1][j] = -4.0f * d[1][j] - 4.0f * d[2][j] + d[3][j] + d[4][j];
        t[2][j] =  4.0f * d[1][j] - 4.0f * d[2][j] - d[3][j] + d[4][j];
        t[3][j] = -2.0f * d[1][j] - 1.0f * d[2][j] + 2.0f * d[3][j] + d[4][j];
        t[4][j] =  2.0f * d[1][j] - 1.0f * d[2][j] - 2.0f * d[3][j] + d[4][j];
        t[5][j] =  4.0f * d[1][j] - 5.0f * d[3][j] + d[5][j];
    }

    int m = n * 1024 + p * 32 + qb * 4 + qt;
    float* vout = g_V + (size_t)m * 64 + ci;
    const size_t plane = (size_t)M_TOT * 64;
#pragma unroll
    for (int a = 0; a < 6; a++) {
        float v0 =  4.0f * t[a][0] - 5.0f * t[a][2] + t[a][4];
        float v1 = -4.0f * t[a][1] - 4.0f * t[a][2] + t[a][3] + t[a][4];
        float v2 =  4.0f * t[a][1] - 4.0f * t[a][2] - t[a][3] + t[a][4];
        float v3 = -2.0f * t[a][1] - 1.0f * t[a][2] + 2.0f * t[a][3] + t[a][4];
        float v4 =  2.0f * t[a][1] - 1.0f * t[a][2] - 2.0f * t[a][3] + t[a][4];
        float v5 =  4.0f * t[a][1] - 5.0f * t[a][3] + t[a][5];
        vout[(a * 6 + 0) * plane] = v0;
        vout[(a * 6 + 1) * plane] = v1;
        vout[(a * 6 + 2) * plane] = v2;
        vout[(a * 6 + 3) * plane] = v3;
        vout[(a * 6 + 4) * plane] = v4;
        vout[(a * 6 + 5) * plane] = v5;
    }
}

// ---------------------------------------------------------------------------
// K3: mma.sync tf32 3-split GEMM.
// grid (128 m-blocks, 36 ab).  CTA: 128m x 64co x K=64, 8 warps.
// Smem: Vs [128][68] float2(hi,lo), Ws [64][68] float2, Ds overlays Vs.
// ---------------------------------------------------------------------------
#define VS_PITCH 68
#define WS_OFF   (128 * VS_PITCH)          // in float2 units
#define GSM_TOTAL ((128 * VS_PITCH + 64 * VS_PITCH) * 8)   // 104448 bytes
#define DS_PITCH 132

__global__ __launch_bounds__(256, 1) void gemm_kernel() {
    extern __shared__ char smem[];
    uint2* Vs = (uint2*)smem;              // [m][VS_PITCH] (hi,lo)
    uint2* Ws = Vs + WS_OFF;               // [co][VS_PITCH]
    float* Ds = (float*)smem;              // [co][DS_PITCH] overlay (after sync)

    int tid = threadIdx.x;
    int ab  = blockIdx.y;
    int m0  = blockIdx.x * 128;

    // ---- fill Vs: 128 x 64, convert fp32 -> (tf32hi, tf32lo) ----
    const float* vsrc = g_V + ((size_t)ab * M_TOT + m0) * 64;
#pragma unroll
    for (int it = 0; it < 8; it++) {
        int t4 = it * 256 + tid;          // 0..2047 float4
        int m  = t4 >> 4;
        int cg = t4 & 15;
        float4 v = *(const float4*)(vsrc + m * 64 + cg * 4);
        uint2* dst = &Vs[m * VS_PITCH + cg * 4];
        float h;
        h = to_tf32(v.x); dst[0] = make_uint2(__float_as_uint(h), __float_as_uint(to_tf32(v.x - h)));
        h = to_tf32(v.y); dst[1] = make_uint2(__float_as_uint(h), __float_as_uint(to_tf32(v.y - h)));
        h = to_tf32(v.z); dst[2] = make_uint2(__float_as_uint(h), __float_as_uint(to_tf32(v.z - h)));
        h = to_tf32(v.w); dst[3] = make_uint2(__float_as_uint(h), __float_as_uint(to_tf32(v.w - h)));
    }
    // ---- fill Ws: 64 x 64 ----
    const float* wsrc = g_Wt + ab * 4096;
#pragma unroll
    for (int it = 0; it < 4; it++) {
        int t4 = it * 256 + tid;          // 0..1023 float4
        int co = t4 >> 4;
        int cg = t4 & 15;
        float4 v = *(const float4*)(wsrc + co * 64 + cg * 4);
        uint2* dst = &Ws[co * VS_PITCH + cg * 4];
        float h;
        h = to_tf32(v.x); dst[0] = make_uint2(__float_as_uint(h), __float_as_uint(to_tf32(v.x - h)));
        h = to_tf32(v.y); dst[1] = make_uint2(__float_as_uint(h), __float_as_uint(to_tf32(v.y - h)));
        h = to_tf32(v.z); dst[2] = make_uint2(__float_as_uint(h), __float_as_uint(to_tf32(v.z - h)));
        h = to_tf32(v.w); dst[3] = make_uint2(__float_as_uint(h), __float_as_uint(to_tf32(v.w - h)));
    }
    __syncthreads();

    // ---- compute ----
    int wid = tid >> 5, lane = tid & 31;
    int mw = wid & 3;        // 4 m-warps x 32 rows
    int nw = wid >> 2;       // 2 co-warps x 32 cols
    int g = lane >> 2, t = lane & 3;

    float acc[2][4][4];
#pragma unroll
    for (int i = 0; i < 2; i++)
#pragma unroll
        for (int j = 0; j < 4; j++)
#pragma unroll
            for (int r = 0; r < 4; r++) acc[i][j][r] = 0.0f;

#pragma unroll
    for (int k0 = 0; k0 < 64; k0 += 8) {
        uint2 a[2][4];
#pragma unroll
        for (int mi = 0; mi < 2; mi++) {
            int rb = mw * 32 + mi * 16 + g;
            a[mi][0] = Vs[(rb)     * VS_PITCH + k0 + t];
            a[mi][1] = Vs[(rb + 8) * VS_PITCH + k0 + t];
            a[mi][2] = Vs[(rb)     * VS_PITCH + k0 + t + 4];
            a[mi][3] = Vs[(rb + 8) * VS_PITCH + k0 + t + 4];
        }
        uint2 b[4][2];
#pragma unroll
        for (int nj = 0; nj < 4; nj++) {
            int co = nw * 32 + nj * 8 + g;
            b[nj][0] = Ws[co * VS_PITCH + k0 + t];
            b[nj][1] = Ws[co * VS_PITCH + k0 + t + 4];
        }
#pragma unroll
        for (int mi = 0; mi < 2; mi++)
#pragma unroll
            for (int nj = 0; nj < 4; nj++) {
                float* d = acc[mi][nj];
                // lo*hi + hi*lo + hi*hi
                mma8(d, a[mi][0].y, a[mi][1].y, a[mi][2].y, a[mi][3].y,
                        b[nj][0].x, b[nj][1].x);
                mma8(d, a[mi][0].x, a[mi][1].x, a[mi][2].x, a[mi][3].x,
                        b[nj][0].y, b[nj][1].y);
                mma8(d, a[mi][0].x, a[mi][1].x, a[mi][2].x, a[mi][3].x,
                        b[nj][0].x, b[nj][1].x);
            }
    }

    // ---- stage D through smem for coalesced M stores ----
    __syncthreads();   // everyone done reading Vs/Ws
#pragma unroll
    for (int mi = 0; mi < 2; mi++)
#pragma unroll
        for (int nj = 0; nj < 4; nj++) {
            int mrow = mw * 32 + mi * 16 + g;
            int co   = nw * 32 + nj * 8 + t * 2;
            Ds[(co)     * DS_PITCH + mrow]     = acc[mi][nj][0];
            Ds[(co + 1) * DS_PITCH + mrow]     = acc[mi][nj][1];
            Ds[(co)     * DS_PITCH + mrow + 8] = acc[mi][nj][2];
            Ds[(co + 1) * DS_PITCH + mrow + 8] = acc[mi][nj][3];
        }
    __syncthreads();

    float* mdst = g_M + (size_t)ab * 64 * M_TOT + m0;
#pragma unroll
    for (int it = 0; it < 8; it++) {
        int idx = it * 256 + tid;         // 0..2047 float4
        int co = idx >> 5;
        int c4 = idx & 31;
        float4 v = *(const float4*)&Ds[co * DS_PITCH + c4 * 4];
        *(float4*)(mdst + (size_t)co * M_TOT + c4 * 4) = v;
    }
}

// ---------------------------------------------------------------------------
// K4: output transform  Y = AT * M * AT^T + bias  (~74% DRAM peak)
// ---------------------------------------------------------------------------
__global__ __launch_bounds__(256) void out_transform(const float* __restrict__ bias,
                                                     float* __restrict__ y) {
    int idx = blockIdx.x * 256 + threadIdx.x;     // co*16384 + m
    int m  = idx & 16383;
    int co = idx >> 14;

    float Mv[6][6];
    const float* msrc = g_M + (size_t)co * M_TOT + m;
    const size_t plane = (size_t)64 * M_TOT;
#pragma unroll
    for (int a = 0; a < 6; a++)
#pragma unroll
        for (int b = 0; b < 6; b++)
            Mv[a][b] = msrc[(a * 6 + b) * plane];

    float P[4][6];
#pragma unroll
    for (int b = 0; b < 6; b++) {
        P[0][b] = Mv[0][b] + Mv[1][b] + Mv[2][b] + Mv[3][b] + Mv[4][b];
        P[1][b] = Mv[1][b] - Mv[2][b] + 2.0f * Mv[3][b] - 2.0f * Mv[4][b];
        P[2][b] = Mv[1][b] + Mv[2][b] + 4.0f * Mv[3][b] + 4.0f * Mv[4][b];
        P[3][b] = Mv[1][b] - Mv[2][b] + 8.0f * Mv[3][b] - 8.0f * Mv[4][b] + Mv[5][b];
    }

    float bv = bias[co];
    int n = m >> 10;
    int p = (m >> 5) & 31;
    int q = m & 31;
    float* yb = y + (((size_t)(n * 64 + co)) * 128 + p * 4) * 128 + q * 4;

#pragma unroll
    for (int xr = 0; xr < 4; xr++) {
        float y0 = P[xr][0] + P[xr][1] + P[xr][2] + P[xr][3] + P[xr][4] + bv;
        float y1 = P[xr][1] - P[xr][2] + 2.0f * P[xr][3] - 2.0f * P[xr][4] + bv;
        float y2 = P[xr][1] + P[xr][2] + 4.0f * P[xr][3] + 4.0f * P[xr][4] + bv;
        float y3 = P[xr][1] - P[xr][2] + 8.0f * P[xr][3] - 8.0f * P[xr][4] + P[xr][5] + bv;
        *(float4*)(yb + xr * 128) = make_float4(y0, y1, y2, y3);
    }
}

// ---------------------------------------------------------------------------
extern "C" void kernel_launch(void* const* d_in, const int* in_sizes, int n_in,
                              void* d_out, int out_size) {
    const float* x = (const float*)d_in[0];   // (16, 64, 128, 128) f32
    const float* w = (const float*)d_in[1];   // (64, 64, 6, 6) f32
    const float* b = (const float*)d_in[2];   // (64,) f32
    float* y = (float*)d_out;                 // (16, 64, 128, 128) f32

    cudaFuncSetAttribute(gemm_kernel, cudaFuncAttributeMaxDynamicSharedMemorySize,
                         GSM_TOTAL);

    wt_kernel<<<(NAB * 64 * 64 + 255) / 256, 256>>>(w);
    in_transform<<<4096, 256>>>(x);
    gemm_kernel<<<dim3(128, 36), 256, GSM_TOTAL>>>();
    out_transform<<<(64 * M_TOT) / 256, 256>>>(b, y);
}